// round 11
// baseline (speedup 1.0000x reference)
#include <cuda_runtime.h>
#include <cuda_fp16.h>
#include <stdint.h>

// out[m] = x[m]·W + b + 0.5*||x[m]V||^2 - 0.5*(sum_i x[m,i])^2 * ||V.sum(0)||^2
// x: (16384,4096) f32, W: (1,4096) f32, b: (1,) f32, V: (4096,128) f32, out f32.
// GEMM fp16 x fp16 -> fp16 acc (V pre-scaled 4096); side sums exact fp32.
// Grid 147 CTAs x 112 rows; pipelined LDSM to hide fragment-load latency.

#define MROWS 16384
#define KDIM  4096
#define NDIM  128
#define KC    64
#define NCH   (KDIM / KC)          // 64
#define NSTRIP 7                   // m16 strips per CTA (112 rows)
#define CTAROWS 112
#define GRID  147                  // 146*112 + 32
#define AROW  144                  // padded smem row stride (bytes)
#define ABUF  (CTAROWS * AROW)     // 16128
#define BBUF  (128 * AROW)         // 18432

#define OF_B   (2 * ABUF)                 // 32256
#define OF_RED (OF_B + 2 * BBUF)          // 69120
#define OF_SXS (OF_RED + CTAROWS * 8 * 4) // 72704
#define OF_SWS (OF_SXS + CTAROWS * 4)     // 73152
#define SMEM_TOTAL (OF_SWS + CTAROWS * 4) // 73600

#define VSCALE 4096.0f
#define T1SCALE (0.5f / (VSCALE * VSCALE))

__device__ __half g_Vt[(size_t)NCH * NDIM * KC];   // chunk-major [c][n][kk], fp16 of 4096*V^T
__device__ float g_spart[256 * NDIM];
__device__ float g_s2;

// ---------------- helpers ----------------

static __device__ __forceinline__ uint32_t smem_u32(const void* p) {
    uint32_t r;
    asm("{ .reg .u64 t; cvta.to.shared.u64 t, %1; cvt.u32.u64 %0, t; }"
        : "=r"(r) : "l"(p));
    return r;
}

static __device__ __forceinline__ uint32_t pack2h(float lo, float hi) {
    __half2 h = __floats2half2_rn(lo, hi);
    return *reinterpret_cast<uint32_t*>(&h);
}

#define MMA_F16(d0, d1, a0, a1, a2, a3, b0, b1)                            \
    asm volatile(                                                          \
        "mma.sync.aligned.m16n8k16.row.col.f16.f16.f16.f16 "               \
        "{%0,%1}, {%2,%3,%4,%5}, {%6,%7}, {%0,%1};"                        \
        : "+r"(d0), "+r"(d1)                                               \
        : "r"(a0), "r"(a1), "r"(a2), "r"(a3), "r"(b0), "r"(b1))

#define LDSM_X4(r0, r1, r2, r3, addr)                                      \
    asm volatile("ldmatrix.sync.aligned.m8n8.x4.shared.b16 "               \
                 "{%0,%1,%2,%3}, [%4];"                                    \
                 : "=r"(r0), "=r"(r1), "=r"(r2), "=r"(r3) : "r"(addr))

// ---------------- prep kernels ----------------

// 256 blocks, block b handles 16 K-rows: k in [16b, 16b+16).
// Row stride 48B in smem (16-byte aligned for the uint4 read phase).
__global__ void prep_kernel(const float* __restrict__ V) {
    __shared__ __align__(16) __half sm[128 * 24];   // 48B row stride
    __shared__ float ps[256];
    const int t = threadIdx.x;
    const int b = blockIdx.x;
    const int k0 = b * 16;
    const int n = t & 127;
    const int half_ = t >> 7;

    float partial = 0.f;
#pragma unroll
    for (int i = 0; i < 8; i++) {
        int kk = 2 * i + half_;
        float v = V[(size_t)(k0 + kk) * NDIM + n];
        partial += v;
        sm[n * 24 + kk] = __float2half_rn(v * VSCALE);
    }
    ps[t] = partial;
    __syncthreads();
    if (t < 128) g_spart[b * 128 + t] = ps[t] + ps[t + 128];

    // out: chunk b>>2, row r, 16B piece at quarter (b&3)*32 + part*16
    const int r = t >> 1, part = t & 1;
    const uint4* src = (const uint4*)((const char*)sm + r * 48 + part * 16);
    uint4 u0 = src[0];
    uint4* dst = (uint4*)((char*)g_Vt + (size_t)(b >> 2) * 16384 + r * 128
                          + (b & 3) * 32 + part * 16);
    dst[0] = u0;
}

__global__ void s2_kernel() {
    __shared__ float sh[128];
    int t = threadIdx.x;
    float s = 0.f;
    for (int b2 = 0; b2 < 256; b2++) s += g_spart[b2 * 128 + t];
    sh[t] = s * s;
    __syncthreads();
    for (int o = 64; o > 0; o >>= 1) {
        if (t < o) sh[t] += sh[t + o];
        __syncthreads();
    }
    if (t == 0) g_s2 = sh[0];
}

// ---------------- main kernel ----------------
// 256 thr = 8 warps; warp w owns n-slice [16w, 16w+16) over ALL 7 m16 strips.
// A/B fragments double-buffered with prefetch so LDSM latency hides under MMA.

__global__ void __launch_bounds__(256, 1) fm_main(
    const float* __restrict__ x, const float* __restrict__ W,
    const float* __restrict__ bias, float* __restrict__ out)
{
    extern __shared__ __align__(16) char smem[];
    float (*red)[8] = (float(*)[8])(smem + OF_RED);
    float* sxs = (float*)(smem + OF_SXS);
    float* sws = (float*)(smem + OF_SWS);

    const int t = threadIdx.x;
    const int wid = t >> 5, lane = t & 31;
    const int mbase = blockIdx.x * CTAROWS;
    const int R = (mbase + CTAROWS <= MROWS) ? CTAROWS : (MROWS - mbase);

    const uint32_t sAu = smem_u32(smem);
    const uint32_t sBu = sAu + OF_B;

    // ---- A gmem row pointers (clamped for the last CTA)
    const float* xrow[NSTRIP];
#pragma unroll
    for (int i = 0; i < NSTRIP; i++) {
        int row = mbase + i * 16 + (t >> 4);
        if (row > MROWS - 1) row = MROWS - 1;
        xrow[i] = x + ((size_t)row << 12) + (t & 15) * 4;
    }
    const char* vb = (const char*)g_Vt + (size_t)t * 16;
    const float4* wp = (const float4*)W + (t & 15);

    // ---- STS addresses
    const uint32_t asts = sAu + (t >> 4) * AROW + (t & 15) * 8;
    const uint32_t bsts = sBu + (t >> 3) * AROW + (t & 7) * 16;

    // ---- ldmatrix addresses
    const uint32_t alds = sAu + (uint32_t)(lane & 15) * AROW + (lane >> 4) * 16;
    const uint32_t blds = sBu + (uint32_t)(wid * 16 + (lane >> 4) * 8 + (lane & 7)) * AROW
                        + ((lane >> 3) & 1) * 16;

    // fp16 packed accumulators: acc[strip][nt] = {c0c1, c2c3}
    uint32_t acc[NSTRIP][2][2];
#pragma unroll
    for (int s = 0; s < NSTRIP; s++)
#pragma unroll
        for (int j = 0; j < 2; j++) { acc[s][j][0] = 0u; acc[s][j][1] = 0u; }

    float sx[NSTRIP], sw[NSTRIP];
#pragma unroll
    for (int i = 0; i < NSTRIP; i++) { sx[i] = 0.f; sw[i] = 0.f; }

    float4 areg[NSTRIP];
    uint4  breg[4];

#define LOADA(c) do {                                                       \
        _Pragma("unroll")                                                   \
        for (int i = 0; i < NSTRIP; i++)                                    \
            areg[i] = *(const float4*)(xrow[i] + (c) * KC);                 \
    } while (0)

#define LOADB(c) do {                                                       \
        _Pragma("unroll")                                                   \
        for (int j = 0; j < 4; j++)                                         \
            breg[j] = *(const uint4*)(vb + (size_t)(c) * 16384 + j * 4096); \
    } while (0)

#define SUMS_STS(c, buf) do {                                               \
        const float4 w4 = wp[(c) * 16];                                     \
        const uint32_t aof_ = (uint32_t)(buf) * ABUF;                       \
        const uint32_t bof_ = (uint32_t)(buf) * BBUF;                       \
        _Pragma("unroll")                                                   \
        for (int i = 0; i < NSTRIP; i++) {                                  \
            const float4 q = areg[i];                                       \
            sx[i] += (q.x + q.y) + (q.z + q.w);                             \
            sw[i] += q.x * w4.x + q.y * w4.y + q.z * w4.z + q.w * w4.w;     \
            const uint32_t p0 = pack2h(q.x, q.y), p1 = pack2h(q.z, q.w);    \
            asm volatile("st.shared.v2.b32 [%0], {%1,%2};"                  \
                         :: "r"(asts + aof_ + i * (16 * AROW)), "r"(p0), "r"(p1)); \
        }                                                                   \
        _Pragma("unroll")                                                   \
        for (int j = 0; j < 4; j++)                                         \
            asm volatile("st.shared.v4.b32 [%0], {%1,%2,%3,%4};"            \
                         :: "r"(bsts + bof_ + j * (32 * AROW)), "r"(breg[j].x), \
                            "r"(breg[j].y), "r"(breg[j].z), "r"(breg[j].w));\
    } while (0)

    // prologue: stage chunk 0
    LOADA(0); LOADB(0);
    SUMS_STS(0, 0);
    __syncthreads();

#pragma unroll 1
    for (int c = 0; c < NCH; c++) {
        const bool more = (c + 1 < NCH);
        if (more) { LOADA(c + 1); LOADB(c + 1); }

        const uint32_t aof = (uint32_t)(c & 1) * ABUF;
        const uint32_t bof = (uint32_t)(c & 1) * BBUF;

        // fragment double buffers
        uint32_t afr[2][4];
        uint32_t bb[2][4];

        // prologue: A(ks0,strip0) and B(ks0)
        LDSM_X4(afr[0][0], afr[0][1], afr[0][2], afr[0][3], alds + aof);
        LDSM_X4(bb[0][0], bb[0][1], bb[0][2], bb[0][3], blds + bof);

#pragma unroll
        for (int ks = 0; ks < 4; ks++) {
#pragma unroll
            for (int s = 0; s < NSTRIP; s++) {
                const int idx = ks * NSTRIP + s;
                const int cur = idx & 1, nxt = (idx + 1) & 1;
                // prefetch next A fragment
                if (s < NSTRIP - 1) {
                    LDSM_X4(afr[nxt][0], afr[nxt][1], afr[nxt][2], afr[nxt][3],
                            alds + aof + ks * 32 + (s + 1) * (16 * AROW));
                } else if (ks < 3) {
                    LDSM_X4(afr[nxt][0], afr[nxt][1], afr[nxt][2], afr[nxt][3],
                            alds + aof + (ks + 1) * 32);
                }
                // prefetch next B mid-stream
                if (s == 3 && ks < 3) {
                    const int bn = (ks + 1) & 1;
                    LDSM_X4(bb[bn][0], bb[bn][1], bb[bn][2], bb[bn][3],
                            blds + bof + (ks + 1) * 32);
                }
                MMA_F16(acc[s][0][0], acc[s][0][1],
                        afr[cur][0], afr[cur][1], afr[cur][2], afr[cur][3],
                        bb[ks & 1][0], bb[ks & 1][1]);
                MMA_F16(acc[s][1][0], acc[s][1][1],
                        afr[cur][0], afr[cur][1], afr[cur][2], afr[cur][3],
                        bb[ks & 1][2], bb[ks & 1][3]);
            }
            if (ks == 2 && more) SUMS_STS(c + 1, (c + 1) & 1);  // STS in MMA shadow
        }
        __syncthreads();
    }

    // ---------------- epilogue ----------------
#pragma unroll
    for (int s = 0; s < NSTRIP; s++) {
        float p0 = 0.f, p1 = 0.f;
#pragma unroll
        for (int nt = 0; nt < 2; nt++) {
            const float2 f0 = __half22float2(*reinterpret_cast<__half2*>(&acc[s][nt][0]));
            const float2 f1 = __half22float2(*reinterpret_cast<__half2*>(&acc[s][nt][1]));
            p0 += f0.x * f0.x + f0.y * f0.y;
            p1 += f1.x * f1.x + f1.y * f1.y;
        }
        p0 += __shfl_xor_sync(0xffffffffu, p0, 1);
        p0 += __shfl_xor_sync(0xffffffffu, p0, 2);
        p1 += __shfl_xor_sync(0xffffffffu, p1, 1);
        p1 += __shfl_xor_sync(0xffffffffu, p1, 2);
        if ((lane & 3) == 0) {
            red[s * 16 + (lane >> 2)][wid]     = p0;
            red[s * 16 + 8 + (lane >> 2)][wid] = p1;
        }
    }

#pragma unroll
    for (int i = 0; i < NSTRIP; i++) {
#pragma unroll
        for (int o = 8; o > 0; o >>= 1) {
            sx[i] += __shfl_xor_sync(0xffffffffu, sx[i], o);
            sw[i] += __shfl_xor_sync(0xffffffffu, sw[i], o);
        }
    }
    if ((t & 15) == 0) {
        const int h = t >> 4;
#pragma unroll
        for (int i = 0; i < NSTRIP; i++) {
            sxs[i * 16 + h] = sx[i];
            sws[i * 16 + h] = sw[i];
        }
    }
    __syncthreads();

    if (t < R) {
        float t1 = 0.f;
#pragma unroll
        for (int w = 0; w < 8; w++) t1 += red[t][w];
        const float s_ = sxs[t];
        out[mbase + t] = sws[t] + bias[0] + T1SCALE * t1 - 0.5f * s_ * s_ * g_s2;
    }
}

// ---------------- launch ----------------

extern "C" void kernel_launch(void* const* d_in, const int* in_sizes, int n_in,
                              void* d_out, int out_size) {
    (void)in_sizes; (void)n_in; (void)out_size;
    const float* x = (const float*)d_in[0];
    const float* W = (const float*)d_in[1];
    const float* b = (const float*)d_in[2];
    const float* V = (const float*)d_in[3];
    float* out = (float*)d_out;

    cudaFuncSetAttribute(fm_main, cudaFuncAttributeMaxDynamicSharedMemorySize, SMEM_TOTAL);

    prep_kernel<<<256, 256>>>(V);
    s2_kernel<<<1, 128>>>();
    fm_main<<<GRID, 256, SMEM_TOTAL>>>(x, W, b, out);
}

// round 12
// speedup vs baseline: 1.1324x; 1.1324x over previous
#include <cuda_runtime.h>
#include <cuda_fp16.h>
#include <stdint.h>

// out[m] = x[m]·W + b + 0.5*||x[m]V||^2 - 0.5*(sum_i x[m,i])^2 * ||V.sum(0)||^2
// x: (16384,4096) f32, W: (1,4096) f32, b: (1,) f32, V: (4096,128) f32, out f32.
// GEMM fp16 x fp16 -> fp16 acc (V pre-scaled 4096); side sums exact fp32.
// Grid 147 x 112 rows (tail CTA overlaps; duplicate writes are identical).
// Batched LDSM->MMA shape (round-8 proven) on the balanced 7-strip layout.

#define MROWS 16384
#define KDIM  4096
#define NDIM  128
#define KC    64
#define NCH   (KDIM / KC)          // 64
#define NSTRIP 7                   // m16 strips per CTA (112 rows)
#define CTAROWS 112
#define GRID  147
#define AROW  144                  // padded smem row stride (bytes)
#define ABUF  (CTAROWS * AROW)     // 16128
#define BBUF  (128 * AROW)         // 18432

#define OF_B   (2 * ABUF)                 // 32256
#define OF_RED (OF_B + 2 * BBUF)          // 69120
#define OF_SXS (OF_RED + CTAROWS * 8 * 4) // 72704
#define OF_SWS (OF_SXS + CTAROWS * 4)     // 73152
#define SMEM_TOTAL (OF_SWS + CTAROWS * 4) // 73600

#define VSCALE 4096.0f
#define T1SCALE (0.5f / (VSCALE * VSCALE))

__device__ __half g_Vt[(size_t)NCH * NDIM * KC];   // chunk-major [c][n][kk], fp16 of 4096*V^T
__device__ float g_spart[256 * NDIM];
__device__ float g_s2;

// ---------------- helpers ----------------

static __device__ __forceinline__ uint32_t smem_u32(const void* p) {
    uint32_t r;
    asm("{ .reg .u64 t; cvta.to.shared.u64 t, %1; cvt.u32.u64 %0, t; }"
        : "=r"(r) : "l"(p));
    return r;
}

static __device__ __forceinline__ uint32_t pack2h(float lo, float hi) {
    __half2 h = __floats2half2_rn(lo, hi);
    return *reinterpret_cast<uint32_t*>(&h);
}

#define MMA_F16(d0, d1, a0, a1, a2, a3, b0, b1)                            \
    asm volatile(                                                          \
        "mma.sync.aligned.m16n8k16.row.col.f16.f16.f16.f16 "               \
        "{%0,%1}, {%2,%3,%4,%5}, {%6,%7}, {%0,%1};"                        \
        : "+r"(d0), "+r"(d1)                                               \
        : "r"(a0), "r"(a1), "r"(a2), "r"(a3), "r"(b0), "r"(b1))

#define LDSM_X4(r0, r1, r2, r3, addr)                                      \
    asm volatile("ldmatrix.sync.aligned.m8n8.x4.shared.b16 "               \
                 "{%0,%1,%2,%3}, [%4];"                                    \
                 : "=r"(r0), "=r"(r1), "=r"(r2), "=r"(r3) : "r"(addr))

// ---------------- prep kernels ----------------

// 256 blocks, block b handles 16 K-rows: k in [16b, 16b+16). 48B smem rows.
__global__ void prep_kernel(const float* __restrict__ V) {
    __shared__ __align__(16) __half sm[128 * 24];
    __shared__ float ps[256];
    const int t = threadIdx.x;
    const int b = blockIdx.x;
    const int k0 = b * 16;
    const int n = t & 127;
    const int half_ = t >> 7;

    float partial = 0.f;
#pragma unroll
    for (int i = 0; i < 8; i++) {
        int kk = 2 * i + half_;
        float v = V[(size_t)(k0 + kk) * NDIM + n];
        partial += v;
        sm[n * 24 + kk] = __float2half_rn(v * VSCALE);
    }
    ps[t] = partial;
    __syncthreads();
    if (t < 128) g_spart[b * 128 + t] = ps[t] + ps[t + 128];

    const int r = t >> 1, part = t & 1;
    const uint4* src = (const uint4*)((const char*)sm + r * 48 + part * 16);
    uint4 u0 = src[0];
    uint4* dst = (uint4*)((char*)g_Vt + (size_t)(b >> 2) * 16384 + r * 128
                          + (b & 3) * 32 + part * 16);
    dst[0] = u0;
}

__global__ void s2_kernel() {
    __shared__ float sh[256];
    __shared__ float sq[128];
    const int t = threadIdx.x;      // 256 threads
    const int n = t & 127, part = t >> 7;
    float s = 0.f;
    for (int b2 = part * 128; b2 < part * 128 + 128; b2++)
        s += g_spart[b2 * 128 + n];
    sh[t] = s;
    __syncthreads();
    if (t < 128) {
        const float tot = sh[t] + sh[t + 128];
        sq[t] = tot * tot;
    }
    __syncthreads();
    for (int o = 64; o > 0; o >>= 1) {
        if (t < o) sq[t] += sq[t + o];
        __syncthreads();
    }
    if (t == 0) g_s2 = sq[0];
}

// ---------------- main kernel ----------------
// 256 thr = 8 warps; warp w owns n-slice [16w,16w+16) over all 7 m16 strips.
// Per k-step: batch 1 B-LDSM + 7 A-LDSM, then 14 independent MMAs (round-8 shape).

__global__ void __launch_bounds__(256, 1) fm_main(
    const float* __restrict__ x, const float* __restrict__ W,
    const float* __restrict__ bias, float* __restrict__ out)
{
    extern __shared__ __align__(16) char smem[];
    float (*red)[8] = (float(*)[8])(smem + OF_RED);
    float* sxs = (float*)(smem + OF_SXS);
    float* sws = (float*)(smem + OF_SWS);

    const int t = threadIdx.x;
    const int wid = t >> 5, lane = t & 31;
    int mbase = blockIdx.x * CTAROWS;
    if (mbase > MROWS - CTAROWS) mbase = MROWS - CTAROWS;  // tail overlap (benign dup writes)

    const uint32_t sAu = smem_u32(smem);
    const uint32_t sBu = sAu + OF_B;

    // ---- gmem pointers: single A base, strip offsets are compile-time consts
    const char* xb = (const char*)x + ((size_t)(mbase + (t >> 4)) << 14) + (t & 15) * 16;
    const char* vb = (const char*)g_Vt + (size_t)t * 16;
    const float4* wp = (const float4*)W + (t & 15);

    // ---- STS addresses
    const uint32_t asts = sAu + (t >> 4) * AROW + (t & 15) * 8;
    const uint32_t bsts = sBu + (t >> 3) * AROW + (t & 7) * 16;

    // ---- ldmatrix addresses
    const uint32_t alds = sAu + (uint32_t)(lane & 15) * AROW + (lane >> 4) * 16;
    const uint32_t blds = sBu + (uint32_t)(wid * 16 + (lane >> 4) * 8 + (lane & 7)) * AROW
                        + ((lane >> 3) & 1) * 16;

    // fp16 packed accumulators: acc[strip][nt] = {c0c1, c2c3}
    uint32_t acc[NSTRIP][2][2];
#pragma unroll
    for (int s = 0; s < NSTRIP; s++)
#pragma unroll
        for (int j = 0; j < 2; j++) { acc[s][j][0] = 0u; acc[s][j][1] = 0u; }

    float sx[NSTRIP], sw[NSTRIP];
#pragma unroll
    for (int i = 0; i < NSTRIP; i++) { sx[i] = 0.f; sw[i] = 0.f; }

    float4 areg[NSTRIP];
    uint4  breg[4];

#define LOADA(c) do {                                                       \
        _Pragma("unroll")                                                   \
        for (int i = 0; i < NSTRIP; i++)                                    \
            areg[i] = *(const float4*)(xb + ((size_t)i << 18) + (c) * 256); \
    } while (0)

#define LOADB(c) do {                                                       \
        _Pragma("unroll")                                                   \
        for (int j = 0; j < 4; j++)                                         \
            breg[j] = *(const uint4*)(vb + (size_t)(c) * 16384 + j * 4096); \
    } while (0)

#define SUMS_STS(c, buf) do {                                               \
        const float4 w4 = wp[(c) * 16];                                     \
        const uint32_t aof_ = (uint32_t)(buf) * ABUF;                       \
        const uint32_t bof_ = (uint32_t)(buf) * BBUF;                       \
        _Pragma("unroll")                                                   \
        for (int i = 0; i < NSTRIP; i++) {                                  \
            const float4 q = areg[i];                                       \
            sx[i] += (q.x + q.y) + (q.z + q.w);                             \
            sw[i] += q.x * w4.x + q.y * w4.y + q.z * w4.z + q.w * w4.w;     \
            const uint32_t p0 = pack2h(q.x, q.y), p1 = pack2h(q.z, q.w);    \
            asm volatile("st.shared.v2.b32 [%0], {%1,%2};"                  \
                         :: "r"(asts + aof_ + i * (16 * AROW)), "r"(p0), "r"(p1)); \
        }                                                                   \
        _Pragma("unroll")                                                   \
        for (int j = 0; j < 4; j++)                                         \
            asm volatile("st.shared.v4.b32 [%0], {%1,%2,%3,%4};"            \
                         :: "r"(bsts + bof_ + j * (32 * AROW)), "r"(breg[j].x), \
                            "r"(breg[j].y), "r"(breg[j].z), "r"(breg[j].w));\
    } while (0)

    // prologue: stage chunk 0
    LOADA(0); LOADB(0);
    SUMS_STS(0, 0);
    __syncthreads();

#pragma unroll 1
    for (int c = 0; c < NCH; c++) {
        const bool more = (c + 1 < NCH);
        if (more) { LOADA(c + 1); LOADB(c + 1); }

        const uint32_t aof = (uint32_t)(c & 1) * ABUF;
        const uint32_t bof = (uint32_t)(c & 1) * BBUF;

#pragma unroll
        for (int ks = 0; ks < 4; ks++) {
            // --- batch all fragment loads for this k-step
            uint32_t bfr[4];
            LDSM_X4(bfr[0], bfr[1], bfr[2], bfr[3], blds + bof + ks * 32);
            uint32_t afr[NSTRIP][4];
#pragma unroll
            for (int s = 0; s < NSTRIP; s++)
                LDSM_X4(afr[s][0], afr[s][1], afr[s][2], afr[s][3],
                        alds + aof + ks * 32 + s * (16 * AROW));
            // --- 14 independent MMAs drain the tensor pipe
#pragma unroll
            for (int s = 0; s < NSTRIP; s++) {
                MMA_F16(acc[s][0][0], acc[s][0][1],
                        afr[s][0], afr[s][1], afr[s][2], afr[s][3],
                        bfr[0], bfr[1]);
                MMA_F16(acc[s][1][0], acc[s][1][1],
                        afr[s][0], afr[s][1], afr[s][2], afr[s][3],
                        bfr[2], bfr[3]);
            }
        }

        if (more) SUMS_STS(c + 1, (c + 1) & 1);
        __syncthreads();
    }

    // ---------------- epilogue ----------------
#pragma unroll
    for (int s = 0; s < NSTRIP; s++) {
        float p0 = 0.f, p1 = 0.f;
#pragma unroll
        for (int nt = 0; nt < 2; nt++) {
            const float2 f0 = __half22float2(*reinterpret_cast<__half2*>(&acc[s][nt][0]));
            const float2 f1 = __half22float2(*reinterpret_cast<__half2*>(&acc[s][nt][1]));
            p0 += f0.x * f0.x + f0.y * f0.y;
            p1 += f1.x * f1.x + f1.y * f1.y;
        }
        p0 += __shfl_xor_sync(0xffffffffu, p0, 1);
        p0 += __shfl_xor_sync(0xffffffffu, p0, 2);
        p1 += __shfl_xor_sync(0xffffffffu, p1, 1);
        p1 += __shfl_xor_sync(0xffffffffu, p1, 2);
        if ((lane & 3) == 0) {
            red[s * 16 + (lane >> 2)][wid]     = p0;
            red[s * 16 + 8 + (lane >> 2)][wid] = p1;
        }
    }

#pragma unroll
    for (int i = 0; i < NSTRIP; i++) {
#pragma unroll
        for (int o = 8; o > 0; o >>= 1) {
            sx[i] += __shfl_xor_sync(0xffffffffu, sx[i], o);
            sw[i] += __shfl_xor_sync(0xffffffffu, sw[i], o);
        }
    }
    if ((t & 15) == 0) {
        const int h = t >> 4;
#pragma unroll
        for (int i = 0; i < NSTRIP; i++) {
            sxs[i * 16 + h] = sx[i];
            sws[i * 16 + h] = sw[i];
        }
    }
    __syncthreads();

    if (t < CTAROWS) {
        float t1 = 0.f;
#pragma unroll
        for (int w = 0; w < 8; w++) t1 += red[t][w];
        const float s_ = sxs[t];
        out[mbase + t] = sws[t] + bias[0] + T1SCALE * t1 - 0.5f * s_ * s_ * g_s2;
    }
}

// ---------------- launch ----------------

extern "C" void kernel_launch(void* const* d_in, const int* in_sizes, int n_in,
                              void* d_out, int out_size) {
    (void)in_sizes; (void)n_in; (void)out_size;
    const float* x = (const float*)d_in[0];
    const float* W = (const float*)d_in[1];
    const float* b = (const float*)d_in[2];
    const float* V = (const float*)d_in[3];
    float* out = (float*)d_out;

    cudaFuncSetAttribute(fm_main, cudaFuncAttributeMaxDynamicSharedMemorySize, SMEM_TOTAL);

    prep_kernel<<<256, 256>>>(V);
    s2_kernel<<<1, 256>>>();
    fm_main<<<GRID, 256, SMEM_TOTAL>>>(x, W, b, out);
}